// round 2
// baseline (speedup 1.0000x reference)
#include <cuda_runtime.h>
#include <math.h>
#include <float.h>
#include <stdint.h>

#define BB   8
#define NN   512
#define CC   256
#define HE   32
#define F0   64
#define OUTD 2

// ---------------- scratch (device globals; no allocations) ----------------
__device__ float g_xa[BB*NN*HE];
__device__ float g_xb[BB*NN*HE];
__device__ float g_e [BB*NN*NN];          // 8 MB
__device__ float g_L0[BB*NN*NN];          // 8 MB
__device__ float g_L1[BB*NN*NN];          // 8 MB (A_pred, then L1 in-place)
__device__ float g_S0[BB*NN];
__device__ float g_S1[BB*NN];
__device__ float g_D0[BB*NN];
__device__ float g_D1[BB*NN];
__device__ float g_xh[BB*NN*2*CC];        // 8 MB
__device__ float g_h0[BB*NN*F0];
__device__ float g_h1[BB*NN*F0];

// ---------------- helpers ----------------
__device__ __forceinline__ float tf32_rn(float x) {
    uint32_t u;
    asm("cvt.rna.tf32.f32 %0, %1;" : "=r"(u) : "f"(x));
    return __uint_as_float(u);
}

__device__ __forceinline__ void mma_tf32(float c[4], const uint32_t a[4], const uint32_t b[2]) {
    asm volatile(
        "mma.sync.aligned.m16n8k8.row.col.f32.tf32.tf32.f32 "
        "{%0,%1,%2,%3}, {%4,%5,%6,%7}, {%8,%9}, {%0,%1,%2,%3};\n"
        : "+f"(c[0]), "+f"(c[1]), "+f"(c[2]), "+f"(c[3])
        : "r"(a[0]), "r"(a[1]), "r"(a[2]), "r"(a[3]), "r"(b[0]), "r"(b[1]));
}

// ---------------- xa = x@ew1[:C], xb = x@ew1[C:] ----------------
__global__ __launch_bounds__(64) void k_xaxb(const float* __restrict__ x,
                                             const float* __restrict__ ew1) {
    int row = blockIdx.x;            // b*N + i
    int t = threadIdx.x;             // 0..63
    __shared__ float xs[CC];
    for (int c = t; c < CC; c += 64) xs[c] = x[row*CC + c];
    __syncthreads();
    int k = t & 31;
    const float* w = ew1 + (t < 32 ? 0 : CC*HE) + k;
    float acc = 0.f;
#pragma unroll 8
    for (int c = 0; c < CC; ++c) acc = fmaf(xs[c], w[c*HE], acc);
    float* dst = (t < 32) ? g_xa : g_xb;
    dst[row*HE + k] = acc;
}

// ---------------- e[b,i,j] = sum_k relu(xa_i+xb_j+eb1)*ew2 + eb2 ----------------
__global__ __launch_bounds__(256) void k_edge(const float* __restrict__ ew2,
                                              const float* __restrict__ eb1,
                                              const float* __restrict__ eb2) {
    int j0 = blockIdx.x*32, i0 = blockIdx.y*32, b = blockIdx.z;
    __shared__ float xas[32][33], xbs[32][33], w[32];
    int t = threadIdx.y*32 + threadIdx.x;
    for (int idx = t; idx < 1024; idx += 256) {
        int r = idx >> 5, k = idx & 31;
        xas[r][k] = g_xa[(b*NN + i0 + r)*HE + k];
        xbs[r][k] = g_xb[(b*NN + j0 + r)*HE + k] + eb1[k];   // fold bias
    }
    if (t < 32) w[t] = ew2[t];
    __syncthreads();
    int tx = threadIdx.x;
    float bias2 = eb2[0];
#pragma unroll
    for (int r = 0; r < 4; ++r) {
        int il = threadIdx.y + r*8;
        float acc = bias2;
#pragma unroll
        for (int k = 0; k < 32; ++k) {
            float v = xas[il][k] + xbs[tx][k];
            acc = fmaf(fmaxf(v, 0.f), w[k], acc);
        }
        g_e[(b*NN + i0 + il)*NN + j0 + tx] = acc;
    }
}

// ---------------- A_pred + fused column-sum into g_S1 ----------------
__global__ __launch_bounds__(256) void k_apred(const float* __restrict__ mask) {
    int j0 = blockIdx.x*32, i0 = blockIdx.y*32, b = blockIdx.z;
    __shared__ float te[32][33];
    __shared__ float mi_s[32], mj_s[32];
    __shared__ float red[8][32];
    int t = threadIdx.y*32 + threadIdx.x;
    for (int idx = t; idx < 1024; idx += 256) {
        int r = idx >> 5, c2 = idx & 31;
        te[r][c2] = g_e[(b*NN + j0 + r)*NN + i0 + c2];  // e tile at (j0,i0)
    }
    if (t < 32) { mi_s[t] = mask[b*NN + i0 + t]; mj_s[t] = mask[b*NN + j0 + t]; }
    __syncthreads();
    int tx = threadIdx.x, ty = threadIdx.y;
    float colacc = 0.f;
#pragma unroll
    for (int r = 0; r < 4; ++r) {
        int il = ty + r*8;
        int gi = i0 + il, gj = j0 + tx;
        float eij = g_e[(b*NN + gi)*NN + gj];
        float eji = te[tx][il];
        float v = 0.f;
        if (gi != gj && mi_s[il] > 0.f && mj_s[tx] > 0.f)
            v = expf(0.5f*(eij + eji));
        g_L1[(b*NN + gi)*NN + gj] = v;
        colacc += v;
    }
    red[ty][tx] = colacc;
    __syncthreads();
    if (ty == 0) {
        float tot = 0.f;
#pragma unroll
        for (int q = 0; q < 8; ++q) tot += red[q][tx];
        atomicAdd(&g_S1[b*NN + j0 + tx], tot);
    }
}

// ---------------- zero the colsum accumulators ----------------
__global__ __launch_bounds__(256) void k_zeroS() {
    int i = blockIdx.x*256 + threadIdx.x;
    if (i < BB*NN) { g_S0[i] = 0.f; g_S1[i] = 0.f; }
}

// ---------------- colsum of A (coalesced rows + atomics) ----------------
__global__ __launch_bounds__(256) void k_colsumA(const float* __restrict__ A) {
    int b = blockIdx.y, r0 = blockIdx.x*64;
    int t = threadIdx.x;
    float a0 = 0.f, a1 = 0.f;
    const float* base = A + ((size_t)b*NN + r0)*NN;
#pragma unroll 4
    for (int r = 0; r < 64; ++r) {
        a0 += base[r*NN + t];
        a1 += base[r*NN + t + 256];
    }
    atomicAdd(&g_S0[b*NN + t],       a0);
    atomicAdd(&g_S0[b*NN + t + 256], a1);
}

// ---------------- D = rsqrt(S + 1 + 1e-5) ----------------
__global__ __launch_bounds__(256) void k_finD() {
    int i = blockIdx.x*256 + threadIdx.x;
    if (i < BB*NN) {
        g_D0[i] = rsqrtf(g_S0[i] + 1.0f + 1e-5f);
        g_D1[i] = rsqrtf(g_S1[i] + 1.0f + 1e-5f);
    }
}

// ---------------- L[b,i,j] = D_i * (A + I)_ij * D_j ----------------
__global__ __launch_bounds__(256) void k_scaleL(const float* __restrict__ Aext, int which) {
    int idx = blockIdx.x*256 + threadIdx.x;   // < B*N*N
    int j = idx & (NN-1);
    int i = (idx >> 9) & (NN-1);
    int b = idx >> 18;
    const float* src = (which == 0) ? Aext : g_L1;
    const float* D   = (which == 0) ? g_D0 : g_D1;
    float* out       = (which == 0) ? g_L0 : g_L1;   // which=1 in-place
    float a = src[idx] + (i == j ? 1.f : 0.f);
    out[idx] = D[b*NN + i] * a * D[b*NN + j];
}

// ---------------- 3xTF32 mma GEMM core: block 128x64, BK=16, 8 warps ----------------
// acc[mt][nt][4]: warp (wm,wn) computes rows wm*32+mt*16+{g,g+8}, cols wn*32+nt*8+2*tig+{0,1}
__device__ __forceinline__ void gemm_core_3xtf32(
    const float* __restrict__ Ag, int lda,
    const float* __restrict__ Bg, int ldb,
    int K, int m0, int n0, float acc[2][4][4])
{
    __shared__ float Ah[16][136], Al[16][136], Bh[16][72], Bl[16][72];
    int t = threadIdx.x;
    int lane = t & 31, warp = t >> 5;
    int g = lane >> 2, tig = lane & 3;
    int wm = warp >> 1, wn = warp & 1;

    for (int k0 = 0; k0 < K; k0 += 16) {
        // A tile: 128 x 16
#pragma unroll
        for (int p = 0; p < 2; ++p) {
            int idx = t + p*256;
            int row = idx >> 2, kq = (idx & 3) * 4;
            float4 v = *(const float4*)&Ag[(size_t)(m0+row)*lda + k0 + kq];
            float vv[4] = {v.x, v.y, v.z, v.w};
#pragma unroll
            for (int j = 0; j < 4; ++j) {
                float hi = tf32_rn(vv[j]);
                Ah[kq+j][row] = hi;
                Al[kq+j][row] = tf32_rn(vv[j] - hi);
            }
        }
        // B tile: 16 x 64
        {
            int kk = t >> 4, nq = (t & 15) * 4;
            float4 v = *(const float4*)&Bg[(size_t)(k0+kk)*ldb + n0 + nq];
            float vv[4] = {v.x, v.y, v.z, v.w};
#pragma unroll
            for (int j = 0; j < 4; ++j) {
                float hi = tf32_rn(vv[j]);
                Bh[kk][nq+j] = hi;
                Bl[kk][nq+j] = tf32_rn(vv[j] - hi);
            }
        }
        __syncthreads();
#pragma unroll
        for (int kb = 0; kb < 16; kb += 8) {
            uint32_t ah[2][4], al[2][4], bh[4][2], bl[4][2];
#pragma unroll
            for (int mt = 0; mt < 2; ++mt) {
                int m = wm*32 + mt*16 + g;
                ah[mt][0] = __float_as_uint(Ah[kb+tig  ][m]);
                ah[mt][1] = __float_as_uint(Ah[kb+tig  ][m+8]);
                ah[mt][2] = __float_as_uint(Ah[kb+tig+4][m]);
                ah[mt][3] = __float_as_uint(Ah[kb+tig+4][m+8]);
                al[mt][0] = __float_as_uint(Al[kb+tig  ][m]);
                al[mt][1] = __float_as_uint(Al[kb+tig  ][m+8]);
                al[mt][2] = __float_as_uint(Al[kb+tig+4][m]);
                al[mt][3] = __float_as_uint(Al[kb+tig+4][m+8]);
            }
#pragma unroll
            for (int nt = 0; nt < 4; ++nt) {
                int n = wn*32 + nt*8 + g;
                bh[nt][0] = __float_as_uint(Bh[kb+tig  ][n]);
                bh[nt][1] = __float_as_uint(Bh[kb+tig+4][n]);
                bl[nt][0] = __float_as_uint(Bl[kb+tig  ][n]);
                bl[nt][1] = __float_as_uint(Bl[kb+tig+4][n]);
            }
#pragma unroll
            for (int mt = 0; mt < 2; ++mt)
#pragma unroll
                for (int nt = 0; nt < 4; ++nt) {
                    mma_tf32(acc[mt][nt], ah[mt], bl[nt]);   // hi*lo
                    mma_tf32(acc[mt][nt], al[mt], bh[nt]);   // lo*hi
                    mma_tf32(acc[mt][nt], ah[mt], bh[nt]);   // hi*hi
                }
        }
        __syncthreads();
    }
}

// ---------------- xh[:, s*F:(s+1)*F] = L_s @ H ----------------
__global__ __launch_bounds__(256) void k_mma_LH(const float* __restrict__ xext,
                                                int hsel, int F) {
    int z = blockIdx.z, b = z >> 1, s = z & 1;
    const float* L = (s ? g_L1 : g_L0) + (size_t)b*NN*NN;
    const float* H = (hsel == 0 ? xext : (hsel == 1 ? g_h0 : g_h1)) + (size_t)b*NN*F;
    float* O = g_xh + (size_t)b*NN*(2*F) + s*F;
    int m0 = blockIdx.y*128, n0 = blockIdx.x*64;
    int ldo = 2*F;

    float acc[2][4][4] = {};
    gemm_core_3xtf32(L, NN, H, F, NN, m0, n0, acc);

    int t = threadIdx.x, lane = t & 31, warp = t >> 5;
    int g = lane >> 2, tig = lane & 3;
    int wm = warp >> 1, wn = warp & 1;
#pragma unroll
    for (int mt = 0; mt < 2; ++mt)
#pragma unroll
        for (int nt = 0; nt < 4; ++nt) {
            int r = m0 + wm*32 + mt*16 + g;
            int cc = n0 + wn*32 + nt*8 + 2*tig;
            *(float2*)&O[(size_t)r*ldo + cc]     = make_float2(acc[mt][nt][0], acc[mt][nt][1]);
            *(float2*)&O[(size_t)(r+8)*ldo + cc] = make_float2(acc[mt][nt][2], acc[mt][nt][3]);
        }
}

// ---------------- Hout = relu((xh @ W + bias) * mask); M = B*N, N=64 ----------------
__global__ __launch_bounds__(256) void k_mma_W(const float* __restrict__ W,
                                               const float* __restrict__ bias,
                                               const float* __restrict__ mask,
                                               int outsel, int K) {
    const float* XH = g_xh;
    float* Hout = outsel ? g_h1 : g_h0;
    int m0 = blockIdx.x*128;

    float acc[2][4][4] = {};
    gemm_core_3xtf32(XH, K, W, F0, K, m0, 0, acc);

    int t = threadIdx.x, lane = t & 31, warp = t >> 5;
    int g = lane >> 2, tig = lane & 3;
    int wm = warp >> 1, wn = warp & 1;
#pragma unroll
    for (int mt = 0; mt < 2; ++mt)
#pragma unroll
        for (int nt = 0; nt < 4; ++nt) {
            int r = m0 + wm*32 + mt*16 + g;
            int cc = wn*32 + nt*8 + 2*tig;
            float b0 = bias[cc], b1 = bias[cc+1];
            float mk0 = mask[r], mk8 = mask[r+8];
            float2 o0, o8;
            o0.x = fmaxf((acc[mt][nt][0] + b0) * mk0, 0.f);
            o0.y = fmaxf((acc[mt][nt][1] + b1) * mk0, 0.f);
            o8.x = fmaxf((acc[mt][nt][2] + b0) * mk8, 0.f);
            o8.y = fmaxf((acc[mt][nt][3] + b1) * mk8, 0.f);
            *(float2*)&Hout[(size_t)r*F0 + cc]     = o0;
            *(float2*)&Hout[(size_t)(r+8)*F0 + cc] = o8;
        }
}

// ---------------- g = max over N; out = g @ fcw + fcb ----------------
__global__ __launch_bounds__(64) void k_final(const float* __restrict__ fcw,
                                              const float* __restrict__ fcb,
                                              float* __restrict__ out) {
    int b = blockIdx.x;
    int f = threadIdx.x;   // 64
    const float* h2 = g_h0;   // layer2 output
    float m = -FLT_MAX;
    for (int i = 0; i < NN; ++i)
        m = fmaxf(m, h2[((size_t)b*NN + i)*F0 + f]);
    __shared__ float gs[F0];
    gs[f] = m;
    __syncthreads();
    if (f < OUTD) {
        float acc = fcb[f];
#pragma unroll
        for (int q = 0; q < F0; ++q) acc = fmaf(gs[q], fcw[q*OUTD + f], acc);
        out[b*OUTD + f] = acc;
    }
}

// ---------------- launch ----------------
extern "C" void kernel_launch(void* const* d_in, const int* in_sizes, int n_in,
                              void* d_out, int out_size) {
    const float* x    = (const float*)d_in[0];
    const float* A    = (const float*)d_in[1];
    const float* mask = (const float*)d_in[2];
    const float* ew1  = (const float*)d_in[3];
    const float* eb1  = (const float*)d_in[4];
    const float* ew2  = (const float*)d_in[5];
    const float* eb2  = (const float*)d_in[6];
    const float* gw0  = (const float*)d_in[7];
    const float* gb0  = (const float*)d_in[8];
    const float* gw1  = (const float*)d_in[9];
    const float* gb1  = (const float*)d_in[10];
    const float* gw2  = (const float*)d_in[11];
    const float* gb2  = (const float*)d_in[12];
    const float* fcw  = (const float*)d_in[13];
    const float* fcb  = (const float*)d_in[14];
    float* out = (float*)d_out;

    k_zeroS<<<16, 256>>>();
    k_xaxb<<<BB*NN, 64>>>(x, ew1);
    k_edge<<<dim3(NN/32, NN/32, BB), dim3(32, 8)>>>(ew2, eb1, eb2);
    k_apred<<<dim3(NN/32, NN/32, BB), dim3(32, 8)>>>(mask);
    k_colsumA<<<dim3(NN/64, BB), 256>>>(A);
    k_finD<<<16, 256>>>();
    k_scaleL<<<(BB*NN*NN)/256, 256>>>(A, 0);
    k_scaleL<<<(BB*NN*NN)/256, 256>>>(A, 1);

    // GCN layer 0: F=256, K=512
    k_mma_LH<<<dim3(CC/64, NN/128, BB*2), 256>>>(x, 0, CC);
    k_mma_W <<<dim3((BB*NN)/128), 256>>>(gw0, gb0, mask, 0, 2*CC);   // -> g_h0

    // GCN layer 1: F=64, K=128
    k_mma_LH<<<dim3(1, NN/128, BB*2), 256>>>(x, 1, F0);
    k_mma_W <<<dim3((BB*NN)/128), 256>>>(gw1, gb1, mask, 1, 2*F0);   // -> g_h1

    // GCN layer 2: F=64, K=128
    k_mma_LH<<<dim3(1, NN/128, BB*2), 256>>>(x, 2, F0);
    k_mma_W <<<dim3((BB*NN)/128), 256>>>(gw2, gb2, mask, 0, 2*F0);   // -> g_h0

    k_final<<<BB, 64>>>(fcw, fcb, out);

    (void)in_sizes; (void)n_in; (void)out_size;
}

// round 3
// speedup vs baseline: 1.2743x; 1.2743x over previous
#include <cuda_runtime.h>
#include <math.h>
#include <float.h>

#define BB   8
#define NN   512
#define CC   256
#define HE   32
#define F0   64
#define OUTD 2
#define MTOT (BB*NN)   // 4096

// ---------------- scratch (device globals; no allocations) ----------------
__device__ float g_xa[MTOT*HE];
__device__ float g_xb[MTOT*HE];
__device__ float g_Ap[BB*NN*NN];     // raw A_pred (8 MB)
__device__ float g_S0[MTOT];
__device__ float g_S1[MTOT];
__device__ float g_D0[MTOT];
__device__ float g_D1[MTOT];
__device__ float g_P0[MTOT*F0];      // D0-scaled projections
__device__ float g_P1[MTOT*F0];
__device__ float g_Y0[MTOT*F0];      // L0 @ P0
__device__ float g_Y1[MTOT*F0];      // L1 @ P1

// ---------------- zero colsum accumulators ----------------
__global__ __launch_bounds__(256) void k_zeroS() {
    int i = blockIdx.x*256 + threadIdx.x;
    if (i < MTOT) { g_S0[i] = 0.f; g_S1[i] = 0.f; }
}

// ---------------- xa = x@ew1[:C], xb = x@ew1[C:] ----------------
__global__ __launch_bounds__(64) void k_xaxb(const float* __restrict__ x,
                                             const float* __restrict__ ew1) {
    int row = blockIdx.x;            // b*N + i
    int t = threadIdx.x;             // 0..63
    __shared__ float xs[CC];
    for (int c = t; c < CC; c += 64) xs[c] = x[row*CC + c];
    __syncthreads();
    int k = t & 31;
    const float* w = ew1 + (t < 32 ? 0 : CC*HE) + k;
    float acc = 0.f;
#pragma unroll 8
    for (int c = 0; c < CC; ++c) acc = fmaf(xs[c], w[c*HE], acc);
    float* dst = (t < 32) ? g_xa : g_xb;
    dst[row*HE + k] = acc;
}

// ---------------- fused edge-MLP + symmetrize + exp + mask + colsum(S1) ----------------
// Upper-triangle 32x32 tile pairs. Writes raw A_pred to g_Ap (every element covered).
__global__ __launch_bounds__(256) void k_edge_sym(const float* __restrict__ mask,
                                                  const float* __restrict__ eb1,
                                                  const float* __restrict__ ew2,
                                                  const float* __restrict__ eb2) {
    int bi = blockIdx.y, bj = blockIdx.x, b = blockIdx.z;
    if (bj < bi) return;
    int i0 = bi*32, j0 = bj*32;
    bool diag = (bi == bj);
    __shared__ float xai[32][33], xbi[32][33], xaj[32][33], xbj[32][33];
    __shared__ float w[32], mi_s[32], mj_s[32];
    __shared__ float red[8][32];
    int tx = threadIdx.x, ty = threadIdx.y;
    int t = ty*32 + tx;
    for (int idx = t; idx < 1024; idx += 256) {
        int r = idx >> 5, k = idx & 31;
        float b1 = eb1[k];
        xai[r][k] = g_xa[(b*NN + i0 + r)*HE + k];
        xbi[r][k] = g_xb[(b*NN + i0 + r)*HE + k] + b1;
        xaj[r][k] = g_xa[(b*NN + j0 + r)*HE + k];
        xbj[r][k] = g_xb[(b*NN + j0 + r)*HE + k] + b1;
    }
    if (t < 32) { w[t] = ew2[t]; mi_s[t] = mask[b*NN + i0 + t]; mj_s[t] = mask[b*NN + j0 + t]; }
    __syncthreads();
    float e2v = eb2[0];
    float colacc = 0.f;
#pragma unroll
    for (int r = 0; r < 4; ++r) {
        int il = ty + r*8, jl = tx;
        float acc1 = e2v, acc2 = e2v;
#pragma unroll
        for (int k = 0; k < 32; ++k) {
            float v1 = xai[il][k] + xbj[jl][k];
            acc1 = fmaf(fmaxf(v1, 0.f), w[k], acc1);
            float v2 = xaj[jl][k] + xbi[il][k];
            acc2 = fmaf(fmaxf(v2, 0.f), w[k], acc2);
        }
        int gi = i0 + il, gj = j0 + jl;
        float v = 0.f;
        if (gi != gj && mi_s[il] > 0.f && mj_s[jl] > 0.f)
            v = expf(0.5f*(acc1 + acc2));
        g_Ap[((size_t)b*NN + gi)*NN + gj] = v;
        colacc += v;
        if (!diag) {
            g_Ap[((size_t)b*NN + gj)*NN + gi] = v;
            // row-sum over jl -> column gi of A_pred (via transposed writes)
            float rs = v;
#pragma unroll
            for (int off = 16; off; off >>= 1) rs += __shfl_xor_sync(0xffffffffu, rs, off);
            if (tx == 0) atomicAdd(&g_S1[b*NN + gi], rs);
        }
    }
    red[ty][tx] = colacc;
    __syncthreads();
    if (ty == 0) {
        float tot = 0.f;
#pragma unroll
        for (int q = 0; q < 8; ++q) tot += red[q][tx];
        atomicAdd(&g_S1[b*NN + j0 + tx], tot);
    }
}

// ---------------- colsum of input A (coalesced rows + atomics into S0) ----------------
__global__ __launch_bounds__(256) void k_colsumA(const float* __restrict__ A) {
    int b = blockIdx.y, r0 = blockIdx.x*64;
    int t = threadIdx.x;
    float a0 = 0.f, a1 = 0.f;
    const float* base = A + ((size_t)b*NN + r0)*NN;
#pragma unroll 4
    for (int r = 0; r < 64; ++r) {
        a0 += base[r*NN + t];
        a1 += base[r*NN + t + 256];
    }
    atomicAdd(&g_S0[b*NN + t],       a0);
    atomicAdd(&g_S0[b*NN + t + 256], a1);
}

// ---------------- D = rsqrt(S + 1 + 1e-5) ----------------
__global__ __launch_bounds__(256) void k_finD() {
    int i = blockIdx.x*256 + threadIdx.x;
    if (i < MTOT) {
        g_D0[i] = rsqrtf(g_S0[i] + 1.0f + 1e-5f);
        g_D1[i] = rsqrtf(g_S1[i] + 1.0f + 1e-5f);
    }
}

// ---------------- projection: P_s = D_s * (h @ W_s) ----------------
// mode 0: h = x (K=CC). mode 1: h = relu((Y0+Y1+biasPrev)*mask) (K=F0).
// blockIdx.y = s selects W rows [s*K, (s+1)*K), D_s, P_s.
__global__ __launch_bounds__(256) void k_proj(const float* __restrict__ xin,
                                              const float* __restrict__ biasPrev,
                                              const float* __restrict__ W,
                                              const float* __restrict__ mask,
                                              int mode, int K) {
    int m0 = blockIdx.x*64;
    int s = blockIdx.y;
    const float* Wp = W + (size_t)s*K*F0;
    const float* Dp = s ? g_D1 : g_D0;
    float* P = s ? g_P1 : g_P0;

    __shared__ float As[16][64];
    __shared__ float Bs[16][64];
    int t = threadIdx.x;
    int tx = t & 15, ty = t >> 4;
    float acc[4][4] = {};

    for (int k0 = 0; k0 < K; k0 += 16) {
        {   // A tile: 64 rows x 16 k (transposed store)
            int row = t >> 2, kq = (t & 3)*4;
            int grow = m0 + row;
            float4 v;
            if (mode == 0) {
                v = *(const float4*)&xin[(size_t)grow*CC + k0 + kq];
            } else {
                float4 y0 = *(const float4*)&g_Y0[(size_t)grow*F0 + k0 + kq];
                float4 y1 = *(const float4*)&g_Y1[(size_t)grow*F0 + k0 + kq];
                float4 bp = *(const float4*)&biasPrev[k0 + kq];
                float mk = mask[grow];
                v.x = fmaxf((y0.x + y1.x + bp.x)*mk, 0.f);
                v.y = fmaxf((y0.y + y1.y + bp.y)*mk, 0.f);
                v.z = fmaxf((y0.z + y1.z + bp.z)*mk, 0.f);
                v.w = fmaxf((y0.w + y1.w + bp.w)*mk, 0.f);
            }
            As[kq+0][row] = v.x; As[kq+1][row] = v.y; As[kq+2][row] = v.z; As[kq+3][row] = v.w;
        }
        {   // B tile: 16 k x 64 n
            int kk = t >> 4, nq = (t & 15)*4;
            *(float4*)&Bs[kk][nq] = *(const float4*)&Wp[(size_t)(k0+kk)*F0 + nq];
        }
        __syncthreads();
#pragma unroll
        for (int k = 0; k < 16; ++k) {
            float4 a = *(const float4*)&As[k][ty*4];
            float4 bv = *(const float4*)&Bs[k][tx*4];
            float av[4] = {a.x, a.y, a.z, a.w};
            float bb[4] = {bv.x, bv.y, bv.z, bv.w};
#pragma unroll
            for (int u = 0; u < 4; ++u)
#pragma unroll
                for (int v2 = 0; v2 < 4; ++v2)
                    acc[u][v2] = fmaf(av[u], bb[v2], acc[u][v2]);
        }
        __syncthreads();
    }
#pragma unroll
    for (int u = 0; u < 4; ++u) {
        int row = m0 + ty*4 + u;
        float d = Dp[row];
        float4 o = make_float4(acc[u][0]*d, acc[u][1]*d, acc[u][2]*d, acc[u][3]*d);
        *(float4*)&P[(size_t)row*F0 + tx*4] = o;
    }
}

// ---------------- Y_s = D_s * (A_s @ P_s + P_s)  (A_s raw; +I and D-scales folded) ----------------
__global__ __launch_bounds__(256) void k_LL(const float* __restrict__ Ain) {
    int m0 = blockIdx.x*64;
    int z = blockIdx.y, b = z >> 1, s = z & 1;
    const float* Am = (s ? g_Ap : Ain) + (size_t)b*NN*NN;
    const float* P  = (s ? g_P1 : g_P0) + (size_t)b*NN*F0;
    float* Y        = (s ? g_Y1 : g_Y0) + (size_t)b*NN*F0;
    const float* D  = (s ? g_D1 : g_D0) + b*NN;

    __shared__ float As[16][64];
    __shared__ float Bs[16][64];
    int t = threadIdx.x;
    int tx = t & 15, ty = t >> 4;
    float acc[4][4] = {};

    for (int k0 = 0; k0 < NN; k0 += 16) {
        {   // A tile: 64 rows x 16 k
            int row = t >> 2, kq = (t & 3)*4;
            float4 v = *(const float4*)&Am[(size_t)(m0+row)*NN + k0 + kq];
            As[kq+0][row] = v.x; As[kq+1][row] = v.y; As[kq+2][row] = v.z; As[kq+3][row] = v.w;
        }
        {   // B tile: 16 k x 64 n
            int kk = t >> 4, nq = (t & 15)*4;
            *(float4*)&Bs[kk][nq] = *(const float4*)&P[(size_t)(k0+kk)*F0 + nq];
        }
        __syncthreads();
#pragma unroll
        for (int k = 0; k < 16; ++k) {
            float4 a = *(const float4*)&As[k][ty*4];
            float4 bv = *(const float4*)&Bs[k][tx*4];
            float av[4] = {a.x, a.y, a.z, a.w};
            float bb[4] = {bv.x, bv.y, bv.z, bv.w};
#pragma unroll
            for (int u = 0; u < 4; ++u)
#pragma unroll
                for (int v2 = 0; v2 < 4; ++v2)
                    acc[u][v2] = fmaf(av[u], bb[v2], acc[u][v2]);
        }
        __syncthreads();
    }
#pragma unroll
    for (int u = 0; u < 4; ++u) {
        int row = m0 + ty*4 + u;
        float d = D[row];
        float4 pd = *(const float4*)&P[(size_t)row*F0 + tx*4];
        float4 o = make_float4(d*(acc[u][0] + pd.x), d*(acc[u][1] + pd.y),
                               d*(acc[u][2] + pd.z), d*(acc[u][3] + pd.w));
        *(float4*)&Y[(size_t)row*F0 + tx*4] = o;
    }
}

// ---------------- final: h = relu((Y0+Y1+gb2)*mask); g = max; out = g@fcw + fcb ----------------
__global__ __launch_bounds__(64) void k_final(const float* __restrict__ gb2,
                                              const float* __restrict__ mask,
                                              const float* __restrict__ fcw,
                                              const float* __restrict__ fcb,
                                              float* __restrict__ out) {
    int b = blockIdx.x;
    int f = threadIdx.x;   // 64
    float bf = gb2[f];
    float m = -FLT_MAX;
    for (int i = 0; i < NN; ++i) {
        int row = b*NN + i;
        float h = fmaxf((g_Y0[(size_t)row*F0 + f] + g_Y1[(size_t)row*F0 + f] + bf)*mask[row], 0.f);
        m = fmaxf(m, h);
    }
    __shared__ float gs[F0];
    gs[f] = m;
    __syncthreads();
    if (f < OUTD) {
        float acc = fcb[f];
#pragma unroll
        for (int q = 0; q < F0; ++q) acc = fmaf(gs[q], fcw[q*OUTD + f], acc);
        out[b*OUTD + f] = acc;
    }
}

// ---------------- launch ----------------
extern "C" void kernel_launch(void* const* d_in, const int* in_sizes, int n_in,
                              void* d_out, int out_size) {
    const float* x    = (const float*)d_in[0];
    const float* A    = (const float*)d_in[1];
    const float* mask = (const float*)d_in[2];
    const float* ew1  = (const float*)d_in[3];
    const float* eb1  = (const float*)d_in[4];
    const float* ew2  = (const float*)d_in[5];
    const float* eb2  = (const float*)d_in[6];
    const float* gw0  = (const float*)d_in[7];
    const float* gb0  = (const float*)d_in[8];
    const float* gw1  = (const float*)d_in[9];
    const float* gb1  = (const float*)d_in[10];
    const float* gw2  = (const float*)d_in[11];
    const float* gb2  = (const float*)d_in[12];
    const float* fcw  = (const float*)d_in[13];
    const float* fcb  = (const float*)d_in[14];
    float* out = (float*)d_out;

    k_zeroS<<<16, 256>>>();
    k_xaxb<<<MTOT, 64>>>(x, ew1);
    k_edge_sym<<<dim3(NN/32, NN/32, BB), dim3(32, 8)>>>(mask, eb1, ew2, eb2);
    k_colsumA<<<dim3(NN/64, BB), 256>>>(A);
    k_finD<<<16, 256>>>();

    // layer 0: P = D*(x@W), Y = D*(A@P + P)
    k_proj<<<dim3(MTOT/64, 2), 256>>>(x, nullptr, gw0, mask, 0, CC);
    k_LL  <<<dim3(NN/64, BB*2), 256>>>(A);

    // layer 1
    k_proj<<<dim3(MTOT/64, 2), 256>>>(nullptr, gb0, gw1, mask, 1, F0);
    k_LL  <<<dim3(NN/64, BB*2), 256>>>(A);

    // layer 2
    k_proj<<<dim3(MTOT/64, 2), 256>>>(nullptr, gb1, gw2, mask, 1, F0);
    k_LL  <<<dim3(NN/64, BB*2), 256>>>(A);

    k_final<<<BB, 64>>>(gb2, mask, fcw, fcb, out);

    (void)in_sizes; (void)n_in; (void)out_size;
}

// round 4
// speedup vs baseline: 1.7505x; 1.3737x over previous
#include <cuda_runtime.h>
#include <math.h>
#include <float.h>
#include <stdint.h>

#define BB   8
#define NN   512
#define CC   256
#define HE   32
#define F0   64
#define OUTD 2
#define MTOT (BB*NN)   // 4096

// ---------------- scratch (device globals; no allocations) ----------------
__device__ float g_xa[MTOT*HE];
__device__ float g_xb[MTOT*HE];
__device__ float g_Ap[BB*NN*NN];     // raw A_pred (8 MB)
__device__ float g_S0[MTOT];
__device__ float g_S1[MTOT];
__device__ float g_D0[MTOT];
__device__ float g_D1[MTOT];
__device__ float g_P0[MTOT*F0];      // D0-scaled projections (tf32-rounded)
__device__ float g_P1[MTOT*F0];
__device__ float g_Y0[MTOT*F0];      // D*(A@P + P)
__device__ float g_Y1[MTOT*F0];

// ---------------- helpers ----------------
__device__ __forceinline__ float tf32_rn(float x) {
    uint32_t u;
    asm("cvt.rna.tf32.f32 %0, %1;" : "=r"(u) : "f"(x));
    return __uint_as_float(u);
}
__device__ __forceinline__ void mma_tf32(float c[4], const uint32_t a[4], const uint32_t b[2]) {
    asm volatile(
        "mma.sync.aligned.m16n8k8.row.col.f32.tf32.tf32.f32 "
        "{%0,%1,%2,%3}, {%4,%5,%6,%7}, {%8,%9}, {%0,%1,%2,%3};\n"
        : "+f"(c[0]), "+f"(c[1]), "+f"(c[2]), "+f"(c[3])
        : "r"(a[0]), "r"(a[1]), "r"(a[2]), "r"(a[3]), "r"(b[0]), "r"(b[1]));
}

// ---------------- zero colsum accumulators ----------------
__global__ __launch_bounds__(256) void k_zeroS() {
    int i = blockIdx.x*256 + threadIdx.x;
    if (i < MTOT) { g_S0[i] = 0.f; g_S1[i] = 0.f; }
}

// ---------------- xa = x@ew1[:C], xb = x@ew1[C:] ----------------
__global__ __launch_bounds__(64) void k_xaxb(const float* __restrict__ x,
                                             const float* __restrict__ ew1) {
    int row = blockIdx.x;
    int t = threadIdx.x;
    __shared__ float xs[CC];
    for (int c = t; c < CC; c += 64) xs[c] = x[row*CC + c];
    __syncthreads();
    int k = t & 31;
    const float* w = ew1 + (t < 32 ? 0 : CC*HE) + k;
    float acc = 0.f;
#pragma unroll 8
    for (int c = 0; c < CC; ++c) acc = fmaf(xs[c], w[c*HE], acc);
    float* dst = (t < 32) ? g_xa : g_xb;
    dst[row*HE + k] = acc;
}

// ---------------- fused edge-MLP + symmetrize + exp + mask + colsum(S1) ----------------
// Triangular grid: blockIdx.x in [0,136) maps to (bi,bj) with bj>=bi.
__global__ __launch_bounds__(256) void k_edge_sym(const float* __restrict__ mask,
                                                  const float* __restrict__ eb1,
                                                  const float* __restrict__ ew2,
                                                  const float* __restrict__ eb2) {
    int idx = blockIdx.x, bi = 0;
    while (idx >= 16 - bi) { idx -= 16 - bi; ++bi; }
    int bj = bi + idx;
    int b = blockIdx.y;
    int i0 = bi*32, j0 = bj*32;
    bool diag = (bi == bj);
    __shared__ float xai[32][33], xbi[32][33], xaj[32][33], xbj[32][33];
    __shared__ float w[32], mi_s[32], mj_s[32];
    __shared__ float red[8][32];
    int tx = threadIdx.x, ty = threadIdx.y;
    int t = ty*32 + tx;
    for (int q = t; q < 1024; q += 256) {
        int r = q >> 5, k = q & 31;
        float b1 = eb1[k];
        xai[r][k] = g_xa[(b*NN + i0 + r)*HE + k];
        xbi[r][k] = g_xb[(b*NN + i0 + r)*HE + k] + b1;
        xaj[r][k] = g_xa[(b*NN + j0 + r)*HE + k];
        xbj[r][k] = g_xb[(b*NN + j0 + r)*HE + k] + b1;
    }
    if (t < 32) { w[t] = ew2[t]; mi_s[t] = mask[b*NN + i0 + t]; mj_s[t] = mask[b*NN + j0 + t]; }
    __syncthreads();
    float e2v = eb2[0];
    float colacc = 0.f;
#pragma unroll
    for (int r = 0; r < 4; ++r) {
        int il = ty + r*8, jl = tx;
        float acc1 = e2v, acc2 = e2v;
#pragma unroll
        for (int k = 0; k < 32; ++k) {
            float v1 = xai[il][k] + xbj[jl][k];
            acc1 = fmaf(fmaxf(v1, 0.f), w[k], acc1);
            float v2 = xaj[jl][k] + xbi[il][k];
            acc2 = fmaf(fmaxf(v2, 0.f), w[k], acc2);
        }
        int gi = i0 + il, gj = j0 + jl;
        float v = 0.f;
        if (gi != gj && mi_s[il] > 0.f && mj_s[jl] > 0.f)
            v = expf(0.5f*(acc1 + acc2));
        g_Ap[((size_t)b*NN + gi)*NN + gj] = v;
        colacc += v;
        if (!diag) {
            g_Ap[((size_t)b*NN + gj)*NN + gi] = v;
            float rs = v;
#pragma unroll
            for (int off = 16; off; off >>= 1) rs += __shfl_xor_sync(0xffffffffu, rs, off);
            if (tx == 0) atomicAdd(&g_S1[b*NN + gi], rs);
        }
    }
    red[ty][tx] = colacc;
    __syncthreads();
    if (ty == 0) {
        float tot = 0.f;
#pragma unroll
        for (int q = 0; q < 8; ++q) tot += red[q][tx];
        atomicAdd(&g_S1[b*NN + j0 + tx], tot);
    }
}

// ---------------- colsum of input A (256 blocks, coalesced) ----------------
__global__ __launch_bounds__(256) void k_colsumA(const float* __restrict__ A) {
    int b = blockIdx.y, r0 = blockIdx.x*16;
    int t = threadIdx.x;
    float a0 = 0.f, a1 = 0.f;
    const float* base = A + ((size_t)b*NN + r0)*NN;
#pragma unroll
    for (int r = 0; r < 16; ++r) {
        a0 += base[r*NN + t];
        a1 += base[r*NN + t + 256];
    }
    atomicAdd(&g_S0[b*NN + t],       a0);
    atomicAdd(&g_S0[b*NN + t + 256], a1);
}

// ---------------- D = rsqrt(S + 1 + 1e-5) ----------------
__global__ __launch_bounds__(256) void k_finD() {
    int i = blockIdx.x*256 + threadIdx.x;
    if (i < MTOT) {
        g_D0[i] = rsqrtf(g_S0[i] + 1.0f + 1e-5f);
        g_D1[i] = rsqrtf(g_S1[i] + 1.0f + 1e-5f);
    }
}

// ---------------- projection: P_s = tf32(D_s * (h @ W_s)) ----------------
__global__ __launch_bounds__(256) void k_proj(const float* __restrict__ xin,
                                              const float* __restrict__ biasPrev,
                                              const float* __restrict__ W,
                                              const float* __restrict__ mask,
                                              int mode, int K) {
    int m0 = blockIdx.x*64;
    int s = blockIdx.y;
    const float* Wp = W + (size_t)s*K*F0;
    const float* Dp = s ? g_D1 : g_D0;
    float* P = s ? g_P1 : g_P0;

    __shared__ float As[16][64];
    __shared__ float Bs[16][64];
    int t = threadIdx.x;
    int tx = t & 15, ty = t >> 4;
    float acc[4][4] = {};

    for (int k0 = 0; k0 < K; k0 += 16) {
        {
            int row = t >> 2, kq = (t & 3)*4;
            int grow = m0 + row;
            float4 v;
            if (mode == 0) {
                v = *(const float4*)&xin[(size_t)grow*CC + k0 + kq];
            } else {
                float4 y0 = *(const float4*)&g_Y0[(size_t)grow*F0 + k0 + kq];
                float4 y1 = *(const float4*)&g_Y1[(size_t)grow*F0 + k0 + kq];
                float4 bp = *(const float4*)&biasPrev[k0 + kq];
                float mk = mask[grow];
                v.x = fmaxf((y0.x + y1.x + bp.x)*mk, 0.f);
                v.y = fmaxf((y0.y + y1.y + bp.y)*mk, 0.f);
                v.z = fmaxf((y0.z + y1.z + bp.z)*mk, 0.f);
                v.w = fmaxf((y0.w + y1.w + bp.w)*mk, 0.f);
            }
            As[kq+0][row] = v.x; As[kq+1][row] = v.y; As[kq+2][row] = v.z; As[kq+3][row] = v.w;
        }
        {
            int kk = t >> 4, nq = (t & 15)*4;
            *(float4*)&Bs[kk][nq] = *(const float4*)&Wp[(size_t)(k0+kk)*F0 + nq];
        }
        __syncthreads();
#pragma unroll
        for (int k = 0; k < 16; ++k) {
            float4 a = *(const float4*)&As[k][ty*4];
            float4 bv = *(const float4*)&Bs[k][tx*4];
            float av[4] = {a.x, a.y, a.z, a.w};
            float bb[4] = {bv.x, bv.y, bv.z, bv.w};
#pragma unroll
            for (int u = 0; u < 4; ++u)
#pragma unroll
                for (int v2 = 0; v2 < 4; ++v2)
                    acc[u][v2] = fmaf(av[u], bb[v2], acc[u][v2]);
        }
        __syncthreads();
    }
#pragma unroll
    for (int u = 0; u < 4; ++u) {
        int row = m0 + ty*4 + u;
        float d = Dp[row];
        float4 o = make_float4(tf32_rn(acc[u][0]*d), tf32_rn(acc[u][1]*d),
                               tf32_rn(acc[u][2]*d), tf32_rn(acc[u][3]*d));
        *(float4*)&P[(size_t)row*F0 + tx*4] = o;
    }
}

// ---------------- Y_s = D_s*(A_s @ P_s + P_s) — single-pass TF32 warp MMA ----------------
// Tile 64x64, 4 warps (2x2), BK=16, register prefetch.
__global__ __launch_bounds__(128) void k_LL_mma(const float* __restrict__ Ain) {
    int m0 = blockIdx.x*64;
    int z = blockIdx.y, b = z >> 1, s = z & 1;
    const float* Am = (s ? g_Ap : Ain) + (size_t)b*NN*NN;
    const float* P  = (s ? g_P1 : g_P0) + (size_t)b*NN*F0;
    float* Y        = (s ? g_Y1 : g_Y0) + (size_t)b*NN*F0;
    const float* D  = (s ? g_D1 : g_D0) + b*NN;

    __shared__ float As[16][72];   // [k][m], stride 72 (mod 32 = 8) conflict-free
    __shared__ float Bs[16][72];   // [k][n]
    int t = threadIdx.x;
    int lane = t & 31, warp = t >> 5;
    int g = lane >> 2, tig = lane & 3;
    int wm = warp >> 1, wn = warp & 1;

    float acc[2][4][4] = {};

    // A quad p: q=t*2+p -> row=q>>2, kq=(q&3)*4 ; B quad: kk=q>>4, nq=(q&15)*4
    int qa0 = t*2, qa1 = t*2 + 1;
    int ar0 = qa0 >> 2, akq0 = (qa0 & 3)*4;
    int ar1 = qa1 >> 2, akq1 = (qa1 & 3)*4;
    int bk0 = qa0 >> 4, bnq0 = (qa0 & 15)*4;
    int bk1 = qa1 >> 4, bnq1 = (qa1 & 15)*4;

    float4 aR0 = *(const float4*)&Am[(size_t)(m0+ar0)*NN + akq0];
    float4 aR1 = *(const float4*)&Am[(size_t)(m0+ar1)*NN + akq1];
    float4 bR0 = *(const float4*)&P[(size_t)bk0*F0 + bnq0];
    float4 bR1 = *(const float4*)&P[(size_t)bk1*F0 + bnq1];

    for (int k0 = 0; k0 < NN; k0 += 16) {
        As[akq0+0][ar0] = tf32_rn(aR0.x); As[akq0+1][ar0] = tf32_rn(aR0.y);
        As[akq0+2][ar0] = tf32_rn(aR0.z); As[akq0+3][ar0] = tf32_rn(aR0.w);
        As[akq1+0][ar1] = tf32_rn(aR1.x); As[akq1+1][ar1] = tf32_rn(aR1.y);
        As[akq1+2][ar1] = tf32_rn(aR1.z); As[akq1+3][ar1] = tf32_rn(aR1.w);
        Bs[bk0][bnq0+0] = bR0.x; Bs[bk0][bnq0+1] = bR0.y;
        Bs[bk0][bnq0+2] = bR0.z; Bs[bk0][bnq0+3] = bR0.w;
        Bs[bk1][bnq1+0] = bR1.x; Bs[bk1][bnq1+1] = bR1.y;
        Bs[bk1][bnq1+2] = bR1.z; Bs[bk1][bnq1+3] = bR1.w;
        __syncthreads();

        if (k0 + 16 < NN) {
            int kn = k0 + 16;
            aR0 = *(const float4*)&Am[(size_t)(m0+ar0)*NN + kn + akq0];
            aR1 = *(const float4*)&Am[(size_t)(m0+ar1)*NN + kn + akq1];
            bR0 = *(const float4*)&P[(size_t)(kn+bk0)*F0 + bnq0];
            bR1 = *(const float4*)&P[(size_t)(kn+bk1)*F0 + bnq1];
        }

#pragma unroll
        for (int kb = 0; kb < 16; kb += 8) {
            uint32_t af[2][4], bf[4][2];
#pragma unroll
            for (int mt = 0; mt < 2; ++mt) {
                int m = wm*32 + mt*16 + g;
                af[mt][0] = __float_as_uint(As[kb+tig  ][m]);
                af[mt][1] = __float_as_uint(As[kb+tig  ][m+8]);
                af[mt][2] = __float_as_uint(As[kb+tig+4][m]);
                af[mt][3] = __float_as_uint(As[kb+tig+4][m+8]);
            }
#pragma unroll
            for (int nt = 0; nt < 4; ++nt) {
                int n = wn*32 + nt*8 + g;
                bf[nt][0] = __float_as_uint(Bs[kb+tig  ][n]);
                bf[nt][1] = __float_as_uint(Bs[kb+tig+4][n]);
            }
#pragma unroll
            for (int mt = 0; mt < 2; ++mt)
#pragma unroll
                for (int nt = 0; nt < 4; ++nt)
                    mma_tf32(acc[mt][nt], af[mt], bf[nt]);
        }
        __syncthreads();
    }

#pragma unroll
    for (int mt = 0; mt < 2; ++mt)
#pragma unroll
        for (int nt = 0; nt < 4; ++nt) {
            int r0 = m0 + wm*32 + mt*16 + g;
            int cc = wn*32 + nt*8 + 2*tig;
            float d0 = D[r0], d8 = D[r0+8];
            float2 p0 = *(const float2*)&P[(size_t)r0*F0 + cc];
            float2 p8 = *(const float2*)&P[(size_t)(r0+8)*F0 + cc];
            float2 o0 = make_float2(d0*(acc[mt][nt][0] + p0.x), d0*(acc[mt][nt][1] + p0.y));
            float2 o8 = make_float2(d8*(acc[mt][nt][2] + p8.x), d8*(acc[mt][nt][3] + p8.y));
            *(float2*)&Y[(size_t)r0*F0 + cc]     = o0;
            *(float2*)&Y[(size_t)(r0+8)*F0 + cc] = o8;
        }
}

// ---------------- final: h = relu((Y0+Y1+gb2)*mask); g = max; out = g@fcw + fcb ----------------
__global__ __launch_bounds__(512) void k_final(const float* __restrict__ gb2,
                                               const float* __restrict__ mask,
                                               const float* __restrict__ fcw,
                                               const float* __restrict__ fcb,
                                               float* __restrict__ out) {
    int b = blockIdx.x;
    int f = threadIdx.x & 63;
    int ty = threadIdx.x >> 6;     // 0..7
    float bf = gb2[f];
    float m = -FLT_MAX;
    for (int i = ty; i < NN; i += 8) {
        int row = b*NN + i;
        float h = fmaxf((g_Y0[(size_t)row*F0 + f] + g_Y1[(size_t)row*F0 + f] + bf)*mask[row], 0.f);
        m = fmaxf(m, h);
    }
    __shared__ float red[8][64];
    __shared__ float gs[F0];
    red[ty][f] = m;
    __syncthreads();
    if (ty == 0) {
        float mm = red[0][f];
#pragma unroll
        for (int q = 1; q < 8; ++q) mm = fmaxf(mm, red[q][f]);
        gs[f] = mm;
    }
    __syncthreads();
    if (threadIdx.x < OUTD) {
        float acc = fcb[threadIdx.x];
#pragma unroll
        for (int q = 0; q < F0; ++q) acc = fmaf(gs[q], fcw[q*OUTD + threadIdx.x], acc);
        out[b*OUTD + threadIdx.x] = acc;
    }
}

// ---------------- launch ----------------
extern "C" void kernel_launch(void* const* d_in, const int* in_sizes, int n_in,
                              void* d_out, int out_size) {
    const float* x    = (const float*)d_in[0];
    const float* A    = (const float*)d_in[1];
    const float* mask = (const float*)d_in[2];
    const float* ew1  = (const float*)d_in[3];
    const float* eb1  = (const float*)d_in[4];
    const float* ew2  = (const float*)d_in[5];
    const float* eb2  = (const float*)d_in[6];
    const float* gw0  = (const float*)d_in[7];
    const float* gb0  = (const float*)d_in[8];
    const float* gw1  = (const float*)d_in[9];
    const float* gb1  = (const float*)d_in[10];
    const float* gw2  = (const float*)d_in[11];
    const float* gb2  = (const float*)d_in[12];
    const float* fcw  = (const float*)d_in[13];
    const float* fcb  = (const float*)d_in[14];
    float* out = (float*)d_out;

    k_zeroS<<<16, 256>>>();
    k_xaxb<<<MTOT, 64>>>(x, ew1);
    k_edge_sym<<<dim3(136, BB), dim3(32, 8)>>>(mask, eb1, ew2, eb2);
    k_colsumA<<<dim3(32, BB), 256>>>(A);
    k_finD<<<16, 256>>>();

    // layer 0
    k_proj<<<dim3(MTOT/64, 2), 256>>>(x, nullptr, gw0, mask, 0, CC);
    k_LL_mma<<<dim3(NN/64, BB*2), 128>>>(A);
    // layer 1
    k_proj<<<dim3(MTOT/64, 2), 256>>>(nullptr, gb0, gw1, mask, 1, F0);
    k_LL_mma<<<dim3(NN/64, BB*2), 128>>>(A);
    // layer 2
    k_proj<<<dim3(MTOT/64, 2), 256>>>(nullptr, gb1, gw2, mask, 1, F0);
    k_LL_mma<<<dim3(NN/64, BB*2), 128>>>(A);

    k_final<<<BB, 512>>>(gb2, mask, fcw, fcb, out);

    (void)in_sizes; (void)n_in; (void)out_size;
}

// round 5
// speedup vs baseline: 2.2454x; 1.2827x over previous
#include <cuda_runtime.h>
#include <math.h>
#include <float.h>
#include <stdint.h>

#define BB   8
#define NN   512
#define CC   256
#define HE   32
#define F0   64
#define OUTD 2
#define MTOT (BB*NN)   // 4096

// ---------------- scratch (device globals; no allocations) ----------------
__device__ float g_xab[MTOT*64];     // [xa | xb+eb1] interleaved per row
__device__ float g_Ap[BB*NN*NN];     // raw A_pred (8 MB)
__device__ float g_S0[MTOT];
__device__ float g_S1[MTOT];
__device__ float g_D0[MTOT];
__device__ float g_D1[MTOT];
__device__ float g_P0[MTOT*F0];      // D-scaled projections (tf32-rounded)
__device__ float g_P1[MTOT*F0];
__device__ float g_Y0[MTOT*F0];
__device__ float g_Y1[MTOT*F0];

// ---------------- helpers ----------------
__device__ __forceinline__ float tf32_rn(float x) {
    uint32_t u;
    asm("cvt.rna.tf32.f32 %0, %1;" : "=r"(u) : "f"(x));
    return __uint_as_float(u);
}
__device__ __forceinline__ void mma_tf32(float c[4], const uint32_t a[4], const uint32_t b[2]) {
    asm volatile(
        "mma.sync.aligned.m16n8k8.row.col.f32.tf32.tf32.f32 "
        "{%0,%1,%2,%3}, {%4,%5,%6,%7}, {%8,%9}, {%0,%1,%2,%3};\n"
        : "+f"(c[0]), "+f"(c[1]), "+f"(c[2]), "+f"(c[3])
        : "r"(a[0]), "r"(a[1]), "r"(a[2]), "r"(a[3]), "r"(b[0]), "r"(b[1]));
}

// ---------------- zero colsum accumulators ----------------
__global__ __launch_bounds__(256) void k_zeroS() {
    int i = blockIdx.x*256 + threadIdx.x;
    if (i < MTOT) { g_S0[i] = 0.f; g_S1[i] = 0.f; }
}

// ---------------- g_xab = x @ [wa | wb], bias eb1 folded into cols 32..63 ----------------
__global__ __launch_bounds__(256) void k_xab(const float* __restrict__ x,
                                             const float* __restrict__ ew1,
                                             const float* __restrict__ eb1) {
    int m0 = blockIdx.x*64;
    __shared__ float As[16][64];
    __shared__ float Bs[16][64];
    int t = threadIdx.x;
    int tx = t & 15, ty = t >> 4;
    float acc[4][4] = {};

    for (int k0 = 0; k0 < CC; k0 += 16) {
        {
            int row = t >> 2, kq = (t & 3)*4;
            float4 v = *(const float4*)&x[(size_t)(m0+row)*CC + k0 + kq];
            As[kq+0][row] = v.x; As[kq+1][row] = v.y; As[kq+2][row] = v.z; As[kq+3][row] = v.w;
        }
        {
            int kk = t >> 4, nq = (t & 15)*4;
            const float* src = (nq < 32) ? &ew1[(size_t)(k0+kk)*HE + nq]
                                         : &ew1[(size_t)(k0+kk+CC)*HE + nq - 32];
            *(float4*)&Bs[kk][nq] = *(const float4*)src;
        }
        __syncthreads();
#pragma unroll
        for (int k = 0; k < 16; ++k) {
            float4 a = *(const float4*)&As[k][ty*4];
            float4 bv = *(const float4*)&Bs[k][tx*4];
            float av[4] = {a.x, a.y, a.z, a.w};
            float bb[4] = {bv.x, bv.y, bv.z, bv.w};
#pragma unroll
            for (int u = 0; u < 4; ++u)
#pragma unroll
                for (int v2 = 0; v2 < 4; ++v2)
                    acc[u][v2] = fmaf(av[u], bb[v2], acc[u][v2]);
        }
        __syncthreads();
    }
#pragma unroll
    for (int u = 0; u < 4; ++u) {
        int row = m0 + ty*4 + u;
        float o[4];
#pragma unroll
        for (int v2 = 0; v2 < 4; ++v2) {
            int col = tx*4 + v2;
            o[v2] = acc[u][v2] + (col >= 32 ? eb1[col-32] : 0.f);
        }
        *(float4*)&g_xab[(size_t)row*64 + tx*4] = make_float4(o[0], o[1], o[2], o[3]);
    }
}

// ---------------- fused edge-MLP + symmetrize + exp + mask + colsum(S1) ----------------
// Triangular grid; j-side operands hoisted to registers (LDS-bound fix).
__global__ __launch_bounds__(256) void k_edge_sym(const float* __restrict__ mask,
                                                  const float* __restrict__ ew2,
                                                  const float* __restrict__ eb2) {
    int idx = blockIdx.x, bi = 0;
    while (idx >= 16 - bi) { idx -= 16 - bi; ++bi; }
    int bj = bi + idx;
    int b = blockIdx.y;
    int i0 = bi*32, j0 = bj*32;
    bool diag = (bi == bj);
    __shared__ float si[32][68], sj[32][68];
    __shared__ float w[32], mi_s[32], mj_s[32];
    __shared__ float red[8][32];
    int tx = threadIdx.x, ty = threadIdx.y;
    int t = ty*32 + tx;
    for (int q = t; q < 512; q += 256) {
        int r = q >> 4, c = (q & 15)*4;
        *(float4*)&si[r][c] = *(const float4*)&g_xab[(size_t)(b*NN + i0 + r)*64 + c];
        *(float4*)&sj[r][c] = *(const float4*)&g_xab[(size_t)(b*NN + j0 + r)*64 + c];
    }
    if (t < 32) { w[t] = ew2[t]; mi_s[t] = mask[b*NN + i0 + t]; mj_s[t] = mask[b*NN + j0 + t]; }
    __syncthreads();

    // hoist j-side (row tx) into registers
    float raj[32], rbj[32];
#pragma unroll
    for (int c = 0; c < 32; c += 4) {
        float4 a = *(const float4*)&sj[tx][c];
        raj[c] = a.x; raj[c+1] = a.y; raj[c+2] = a.z; raj[c+3] = a.w;
        float4 bq = *(const float4*)&sj[tx][32 + c];
        rbj[c] = bq.x; rbj[c+1] = bq.y; rbj[c+2] = bq.z; rbj[c+3] = bq.w;
    }

    float e2v = eb2[0];
    float colacc = 0.f;
#pragma unroll
    for (int r = 0; r < 4; ++r) {
        int il = ty + r*8, jl = tx;
        float acc1 = e2v, acc2 = e2v;
#pragma unroll
        for (int k = 0; k < 32; ++k) {
            float ai = si[il][k];           // broadcast
            float bi_ = si[il][32 + k];     // broadcast (includes eb1)
            float v1 = ai + rbj[k];
            acc1 = fmaf(fmaxf(v1, 0.f), w[k], acc1);
            float v2 = raj[k] + bi_;
            acc2 = fmaf(fmaxf(v2, 0.f), w[k], acc2);
        }
        int gi = i0 + il, gj = j0 + jl;
        float v = 0.f;
        if (gi != gj && mi_s[il] > 0.f && mj_s[jl] > 0.f)
            v = expf(0.5f*(acc1 + acc2));
        g_Ap[((size_t)b*NN + gi)*NN + gj] = v;
        colacc += v;
        if (!diag) {
            g_Ap[((size_t)b*NN + gj)*NN + gi] = v;
            float rs = v;
#pragma unroll
            for (int off = 16; off; off >>= 1) rs += __shfl_xor_sync(0xffffffffu, rs, off);
            if (tx == 0) atomicAdd(&g_S1[b*NN + gi], rs);
        }
    }
    red[ty][tx] = colacc;
    __syncthreads();
    if (ty == 0) {
        float tot = 0.f;
#pragma unroll
        for (int q = 0; q < 8; ++q) tot += red[q][tx];
        atomicAdd(&g_S1[b*NN + j0 + tx], tot);
    }
}

// ---------------- colsum of input A ----------------
__global__ __launch_bounds__(256) void k_colsumA(const float* __restrict__ A) {
    int b = blockIdx.y, r0 = blockIdx.x*16;
    int t = threadIdx.x;
    float a0 = 0.f, a1 = 0.f;
    const float* base = A + ((size_t)b*NN + r0)*NN;
#pragma unroll
    for (int r = 0; r < 16; ++r) {
        a0 += base[r*NN + t];
        a1 += base[r*NN + t + 256];
    }
    atomicAdd(&g_S0[b*NN + t],       a0);
    atomicAdd(&g_S0[b*NN + t + 256], a1);
}

// ---------------- D = rsqrt(S + 1 + 1e-5) ----------------
__global__ __launch_bounds__(256) void k_finD() {
    int i = blockIdx.x*256 + threadIdx.x;
    if (i < MTOT) {
        g_D0[i] = rsqrtf(g_S0[i] + 1.0f + 1e-5f);
        g_D1[i] = rsqrtf(g_S1[i] + 1.0f + 1e-5f);
    }
}

// ---------------- projection: P_s = tf32(D_s * (h @ W_s)) ----------------
__global__ __launch_bounds__(256) void k_proj(const float* __restrict__ xin,
                                              const float* __restrict__ biasPrev,
                                              const float* __restrict__ W,
                                              const float* __restrict__ mask,
                                              int mode, int K) {
    int m0 = blockIdx.x*64;
    int s = blockIdx.y;
    const float* Wp = W + (size_t)s*K*F0;
    const float* Dp = s ? g_D1 : g_D0;
    float* P = s ? g_P1 : g_P0;

    __shared__ float As[16][64];
    __shared__ float Bs[16][64];
    int t = threadIdx.x;
    int tx = t & 15, ty = t >> 4;
    float acc[4][4] = {};

    for (int k0 = 0; k0 < K; k0 += 16) {
        {
            int row = t >> 2, kq = (t & 3)*4;
            int grow = m0 + row;
            float4 v;
            if (mode == 0) {
                v = *(const float4*)&xin[(size_t)grow*CC + k0 + kq];
            } else {
                float4 y0 = *(const float4*)&g_Y0[(size_t)grow*F0 + k0 + kq];
                float4 y1 = *(const float4*)&g_Y1[(size_t)grow*F0 + k0 + kq];
                float4 bp = *(const float4*)&biasPrev[k0 + kq];
                float mk = mask[grow];
                v.x = fmaxf((y0.x + y1.x + bp.x)*mk, 0.f);
                v.y = fmaxf((y0.y + y1.y + bp.y)*mk, 0.f);
                v.z = fmaxf((y0.z + y1.z + bp.z)*mk, 0.f);
                v.w = fmaxf((y0.w + y1.w + bp.w)*mk, 0.f);
            }
            As[kq+0][row] = v.x; As[kq+1][row] = v.y; As[kq+2][row] = v.z; As[kq+3][row] = v.w;
        }
        {
            int kk = t >> 4, nq = (t & 15)*4;
            *(float4*)&Bs[kk][nq] = *(const float4*)&Wp[(size_t)(k0+kk)*F0 + nq];
        }
        __syncthreads();
#pragma unroll
        for (int k = 0; k < 16; ++k) {
            float4 a = *(const float4*)&As[k][ty*4];
            float4 bv = *(const float4*)&Bs[k][tx*4];
            float av[4] = {a.x, a.y, a.z, a.w};
            float bb[4] = {bv.x, bv.y, bv.z, bv.w};
#pragma unroll
            for (int u = 0; u < 4; ++u)
#pragma unroll
                for (int v2 = 0; v2 < 4; ++v2)
                    acc[u][v2] = fmaf(av[u], bb[v2], acc[u][v2]);
        }
        __syncthreads();
    }
#pragma unroll
    for (int u = 0; u < 4; ++u) {
        int row = m0 + ty*4 + u;
        float d = Dp[row];
        float4 o = make_float4(tf32_rn(acc[u][0]*d), tf32_rn(acc[u][1]*d),
                               tf32_rn(acc[u][2]*d), tf32_rn(acc[u][3]*d));
        *(float4*)&P[(size_t)row*F0 + tx*4] = o;
    }
}

// ---------------- Y_s = D_s*(A_s @ P_s + P_s) — TF32 MMA, in-block split-K ----------------
// 256 threads = 2 groups of 4 warps; group gq handles k = gq*16 step 32.
__global__ __launch_bounds__(256) void k_LL_mma(const float* __restrict__ Ain) {
    int m0 = blockIdx.x*64;
    int z = blockIdx.y, b = z >> 1, s = z & 1;
    const float* Am = (s ? g_Ap : Ain) + (size_t)b*NN*NN;
    const float* P  = (s ? g_P1 : g_P0) + (size_t)b*NN*F0;
    float* Y        = (s ? g_Y1 : g_Y0) + (size_t)b*NN*F0;
    const float* D  = (s ? g_D1 : g_D0) + b*NN;

    __shared__ float As[2][16][72];
    __shared__ float Bs[2][16][72];
    __shared__ float red[4096];      // 16 KB cross-group reduction
    int t = threadIdx.x;
    int lane = t & 31, warp = t >> 5;
    int gq = warp >> 2, wg = warp & 3;
    int g = lane >> 2, tig = lane & 3;
    int wm = wg >> 1, wn = wg & 1;
    int tg = t & 127;

    float acc[2][4][4] = {};

    int qa0 = tg*2, qa1 = tg*2 + 1;
    int ar0 = qa0 >> 2, akq0 = (qa0 & 3)*4;
    int ar1 = qa1 >> 2, akq1 = (qa1 & 3)*4;
    int bk0 = qa0 >> 4, bnq0 = (qa0 & 15)*4;
    int bk1 = qa1 >> 4, bnq1 = (qa1 & 15)*4;

    int kstart = gq*16;
    float4 aR0 = *(const float4*)&Am[(size_t)(m0+ar0)*NN + kstart + akq0];
    float4 aR1 = *(const float4*)&Am[(size_t)(m0+ar1)*NN + kstart + akq1];
    float4 bR0 = *(const float4*)&P[(size_t)(kstart+bk0)*F0 + bnq0];
    float4 bR1 = *(const float4*)&P[(size_t)(kstart+bk1)*F0 + bnq1];

    for (int k0 = kstart; k0 < NN; k0 += 32) {
        As[gq][akq0+0][ar0] = tf32_rn(aR0.x); As[gq][akq0+1][ar0] = tf32_rn(aR0.y);
        As[gq][akq0+2][ar0] = tf32_rn(aR0.z); As[gq][akq0+3][ar0] = tf32_rn(aR0.w);
        As[gq][akq1+0][ar1] = tf32_rn(aR1.x); As[gq][akq1+1][ar1] = tf32_rn(aR1.y);
        As[gq][akq1+2][ar1] = tf32_rn(aR1.z); As[gq][akq1+3][ar1] = tf32_rn(aR1.w);
        Bs[gq][bk0][bnq0+0] = bR0.x; Bs[gq][bk0][bnq0+1] = bR0.y;
        Bs[gq][bk0][bnq0+2] = bR0.z; Bs[gq][bk0][bnq0+3] = bR0.w;
        Bs[gq][bk1][bnq1+0] = bR1.x; Bs[gq][bk1][bnq1+1] = bR1.y;
        Bs[gq][bk1][bnq1+2] = bR1.z; Bs[gq][bk1][bnq1+3] = bR1.w;
        __syncthreads();

        if (k0 + 32 < NN) {
            int kn = k0 + 32;
            aR0 = *(const float4*)&Am[(size_t)(m0+ar0)*NN + kn + akq0];
            aR1 = *(const float4*)&Am[(size_t)(m0+ar1)*NN + kn + akq1];
            bR0 = *(const float4*)&P[(size_t)(kn+bk0)*F0 + bnq0];
            bR1 = *(const float4*)&P[(size_t)(kn+bk1)*F0 + bnq1];
        }

#pragma unroll
        for (int kb = 0; kb < 16; kb += 8) {
            uint32_t af[2][4], bf[4][2];
#pragma unroll
            for (int mt = 0; mt < 2; ++mt) {
                int m = wm*32 + mt*16 + g;
                af[mt][0] = __float_as_uint(As[gq][kb+tig  ][m]);
                af[mt][1] = __float_as_uint(As[gq][kb+tig  ][m+8]);
                af[mt][2] = __float_as_uint(As[gq][kb+tig+4][m]);
                af[mt][3] = __float_as_uint(As[gq][kb+tig+4][m+8]);
            }
#pragma unroll
            for (int nt = 0; nt < 4; ++nt) {
                int n = wn*32 + nt*8 + g;
                bf[nt][0] = __float_as_uint(Bs[gq][kb+tig  ][n]);
                bf[nt][1] = __float_as_uint(Bs[gq][kb+tig+4][n]);
            }
#pragma unroll
            for (int mt = 0; mt < 2; ++mt)
#pragma unroll
                for (int nt = 0; nt < 4; ++nt)
                    mma_tf32(acc[mt][nt], af[mt], bf[nt]);
        }
        __syncthreads();
    }

    // cross-group reduction: group 1 writes, group 0 adds + epilogue
    if (gq == 1) {
#pragma unroll
        for (int mt = 0; mt < 2; ++mt)
#pragma unroll
            for (int nt = 0; nt < 4; ++nt)
                *(float4*)&red[(((wg*2+mt)*4+nt)*32 + lane)*4] =
                    make_float4(acc[mt][nt][0], acc[mt][nt][1], acc[mt][nt][2], acc[mt][nt][3]);
    }
    __syncthreads();
    if (gq == 0) {
#pragma unroll
        for (int mt = 0; mt < 2; ++mt)
#pragma unroll
            for (int nt = 0; nt < 4; ++nt) {
                float4 rv = *(const float4*)&red[(((wg*2+mt)*4+nt)*32 + lane)*4];
                float c0 = acc[mt][nt][0] + rv.x;
                float c1 = acc[mt][nt][1] + rv.y;
                float c2 = acc[mt][nt][2] + rv.z;
                float c3 = acc[mt][nt][3] + rv.w;
                int r0 = m0 + wm*32 + mt*16 + g;
                int cc = wn*32 + nt*8 + 2*tig;
                float d0 = D[r0], d8 = D[r0+8];
                float2 p0 = *(const float2*)&P[(size_t)r0*F0 + cc];
                float2 p8 = *(const float2*)&P[(size_t)(r0+8)*F0 + cc];
                *(float2*)&Y[(size_t)r0*F0 + cc]     = make_float2(d0*(c0 + p0.x), d0*(c1 + p0.y));
                *(float2*)&Y[(size_t)(r0+8)*F0 + cc] = make_float2(d8*(c2 + p8.x), d8*(c3 + p8.y));
            }
    }
}

// ---------------- final: h = relu((Y0+Y1+gb2)*mask); g = max; out = g@fcw + fcb ----------------
__global__ __launch_bounds__(512) void k_final(const float* __restrict__ gb2,
                                               const float* __restrict__ mask,
                                               const float* __restrict__ fcw,
                                               const float* __restrict__ fcb,
                                               float* __restrict__ out) {
    int b = blockIdx.x;
    int f = threadIdx.x & 63;
    int ty = threadIdx.x >> 6;
    float bf = gb2[f];
    float m = -FLT_MAX;
    for (int i = ty; i < NN; i += 8) {
        int row = b*NN + i;
        float h = fmaxf((g_Y0[(size_t)row*F0 + f] + g_Y1[(size_t)row*F0 + f] + bf)*mask[row], 0.f);
        m = fmaxf(m, h);
    }
    __shared__ float red[8][64];
    __shared__ float gs[F0];
    red[ty][f] = m;
    __syncthreads();
    if (ty == 0) {
        float mm = red[0][f];
#pragma unroll
        for (int q = 1; q < 8; ++q) mm = fmaxf(mm, red[q][f]);
        gs[f] = mm;
    }
    __syncthreads();
    if (threadIdx.x < OUTD) {
        float acc = fcb[threadIdx.x];
#pragma unroll
        for (int q = 0; q < F0; ++q) acc = fmaf(gs[q], fcw[q*OUTD + threadIdx.x], acc);
        out[b*OUTD + threadIdx.x] = acc;
    }
}

// ---------------- launch ----------------
extern "C" void kernel_launch(void* const* d_in, const int* in_sizes, int n_in,
                              void* d_out, int out_size) {
    const float* x    = (const float*)d_in[0];
    const float* A    = (const float*)d_in[1];
    const float* mask = (const float*)d_in[2];
    const float* ew1  = (const float*)d_in[3];
    const float* eb1  = (const float*)d_in[4];
    const float* ew2  = (const float*)d_in[5];
    const float* eb2  = (const float*)d_in[6];
    const float* gw0  = (const float*)d_in[7];
    const float* gb0  = (const float*)d_in[8];
    const float* gw1  = (const float*)d_in[9];
    const float* gb1  = (const float*)d_in[10];
    const float* gw2  = (const float*)d_in[11];
    const float* gb2  = (const float*)d_in[12];
    const float* fcw  = (const float*)d_in[13];
    const float* fcb  = (const float*)d_in[14];
    float* out = (float*)d_out;

    k_zeroS<<<16, 256>>>();
    k_xab<<<MTOT/64, 256>>>(x, ew1, eb1);
    k_edge_sym<<<dim3(136, BB), dim3(32, 8)>>>(mask, ew2, eb2);
    k_colsumA<<<dim3(32, BB), 256>>>(A);
    k_finD<<<16, 256>>>();

    // layer 0
    k_proj<<<dim3(MTOT/64, 2), 256>>>(x, nullptr, gw0, mask, 0, CC);
    k_LL_mma<<<dim3(NN/64, BB*2), 256>>>(A);
    // layer 1
    k_proj<<<dim3(MTOT/64, 2), 256>>>(nullptr, gb0, gw1, mask, 1, F0);
    k_LL_mma<<<dim3(NN/64, BB*2), 256>>>(A);
    // layer 2
    k_proj<<<dim3(MTOT/64, 2), 256>>>(nullptr, gb1, gw2, mask, 1, F0);
    k_LL_mma<<<dim3(NN/64, BB*2), 256>>>(A);

    k_final<<<BB, 512>>>(gb2, mask, fcw, fcb, out);

    (void)in_sizes; (void)n_in; (void)out_size;
}